// round 3
// baseline (speedup 1.0000x reference)
#include <cuda_runtime.h>

#define Bdim  32
#define Hdim  256
#define INdim 256
#define T_MAX 2048
#define KS    224                      // W_rec^T rows kept in shared memory
#define NLOOP 32                       // loop CTAs (one per batch)
#define LOOP_SMEM (KS * Hdim * 4 + 64) // 229440 <= 232448 (227KB cap)

__device__ float g_Iin[(size_t)T_MAX * Bdim * Hdim];  // input currents (t,b,h)
__device__ float g_WT[Hdim * Hdim];                    // WT[k][h] = Wrec[h][k]
__device__ int   g_chunk_done[64];                     // tiles finished per 64-step chunk

// ---------------------------------------------------------------------------
// Init: zero chunk flags, build transposed recurrent weights. Runs each launch.
// ---------------------------------------------------------------------------
__global__ void init_kernel(const float* __restrict__ Wrec)
{
    int tid = blockIdx.x * blockDim.x + threadIdx.x;
    if (tid < 64) g_chunk_done[tid] = 0;
    for (int idx = tid; idx < Hdim * Hdim; idx += gridDim.x * blockDim.x) {
        int k = idx >> 8;
        int h = idx & 255;
        g_WT[idx] = Wrec[h * Hdim + k];
    }
}

// ---------------------------------------------------------------------------
// Fused persistent kernel. blockIdx < NLOOP: LIF recurrence (1 CTA / batch).
// blockIdx >= NLOOP: fp32 NT GEMM C[m][h] = sum_k x[m][k]*Win[h][k] into
// g_Iin, tiles in t-major order, publishing per-chunk completion counters.
// 227KB smem/CTA forces 1 CTA/SM; grid == #SMs, so all CTAs are wave-1
// co-resident and the producer/consumer handshake cannot deadlock.
// ---------------------------------------------------------------------------
__global__ __launch_bounds__(256, 1) void fused_kernel(
    const float* __restrict__ x,   const float* __restrict__ z0,
    const float* __restrict__ v0,  const float* __restrict__ i0,
    const float* __restrict__ Win, float* __restrict__ out, int T)
{
    extern __shared__ float smem[];
    const int tid = threadIdx.x;

    if (blockIdx.x >= NLOOP) {
        // ================= GEMM producer =================
        float (*As)[132] = (float (*)[132])smem;
        float (*Bs)[132] = (float (*)[132])(smem + 32 * 132);
        const int g  = blockIdx.x - NLOOP;
        const int NG = gridDim.x - NLOOP;
        const int M  = T * Bdim;
        const int ntiles = (M / 128) * (Hdim / 128);
        const int tx = tid & 15;
        const int ty = tid >> 4;

        for (int tile = g; tile < ntiles; tile += NG) {
            const int m0 = (tile >> 1) * 128;
            const int n0 = (tile & 1) * 128;
            float acc[8][8];
#pragma unroll
            for (int r = 0; r < 8; ++r)
#pragma unroll
                for (int c = 0; c < 8; ++c) acc[r][c] = 0.0f;

            for (int k0 = 0; k0 < INdim; k0 += 32) {
#pragma unroll
                for (int i = 0; i < 4; ++i) {
                    int idx = tid + i * 256;
                    int row = idx >> 3;
                    int c4  = idx & 7;
                    float4 av = *(const float4*)(x + (size_t)(m0 + row) * INdim + k0 + c4 * 4);
                    As[c4 * 4 + 0][row] = av.x;
                    As[c4 * 4 + 1][row] = av.y;
                    As[c4 * 4 + 2][row] = av.z;
                    As[c4 * 4 + 3][row] = av.w;
                    float4 bv = *(const float4*)(Win + (size_t)(n0 + row) * INdim + k0 + c4 * 4);
                    Bs[c4 * 4 + 0][row] = bv.x;
                    Bs[c4 * 4 + 1][row] = bv.y;
                    Bs[c4 * 4 + 2][row] = bv.z;
                    Bs[c4 * 4 + 3][row] = bv.w;
                }
                __syncthreads();
#pragma unroll
                for (int k = 0; k < 32; ++k) {
                    float a[8], b[8];
#pragma unroll
                    for (int u = 0; u < 8; u += 4) {
                        float4 t4 = *(const float4*)&As[k][ty * 8 + u];
                        a[u] = t4.x; a[u + 1] = t4.y; a[u + 2] = t4.z; a[u + 3] = t4.w;
                        float4 s4 = *(const float4*)&Bs[k][tx * 8 + u];
                        b[u] = s4.x; b[u + 1] = s4.y; b[u + 2] = s4.z; b[u + 3] = s4.w;
                    }
#pragma unroll
                    for (int r = 0; r < 8; ++r)
#pragma unroll
                        for (int c = 0; c < 8; ++c)
                            acc[r][c] = fmaf(a[r], b[c], acc[r][c]);
                }
                __syncthreads();
            }
#pragma unroll
            for (int r = 0; r < 8; ++r)
#pragma unroll
                for (int c = 0; c < 8; c += 4) {
                    float4 o = make_float4(acc[r][c], acc[r][c + 1], acc[r][c + 2], acc[r][c + 3]);
                    *(float4*)(g_Iin + (size_t)(m0 + ty * 8 + r) * Hdim + n0 + tx * 8 + c) = o;
                }
            __threadfence();            // publish this thread's tile stores
            __syncthreads();            // all threads' stores fenced
            if (tid == 0) atomicAdd(&g_chunk_done[m0 >> 11], 1);  // chunk = (m0/128)/16
        }
        return;
    }

    // ================= LIF recurrence consumer =================
    const int b = blockIdx.x;
    float*    Wsh   = smem;                              // [KS][Hdim]
    unsigned* masks = (unsigned*)(smem + KS * Hdim);     // [2][8] spike bitmasks

    // Stage W^T rows [0,KS) into smem (coalesced float4 from g_WT).
    for (int idx = tid; idx < KS * Hdim / 4; idx += 256)
        ((float4*)Wsh)[idx] = ((const float4*)g_WT)[idx];

    const bool worker = tid < 128;
    const int  j    = tid;          // worker's pair index: neurons 2j, 2j+1
    const int  warp = tid >> 5;
    const int  lane = tid & 31;

    float v0r = 0.f, v1r = 0.f, c0 = 0.f, c1 = 0.f;
    float2 wreg[32];                // rows [KS,256) for cols 2j,2j+1
    bool zA = false, zB = false;

    if (worker) {
        float2 zz = *(const float2*)(z0 + b * Hdim + 2 * j);
        float2 vv = *(const float2*)(v0 + b * Hdim + 2 * j);
        float2 ii = *(const float2*)(i0 + b * Hdim + 2 * j);
        v0r = vv.x; v1r = vv.y; c0 = ii.x; c1 = ii.y;
        unsigned mA = __ballot_sync(0xffffffffu, zz.x != 0.0f);
        unsigned mB = __ballot_sync(0xffffffffu, zz.y != 0.0f);
        if (lane == 0) { masks[2 * warp] = mA; masks[2 * warp + 1] = mB; }
#pragma unroll
        for (int r = 0; r < 32; ++r)
            wreg[r] = *(const float2*)(g_WT + (size_t)(KS + r) * Hdim + 2 * j);
    }
    if (tid == 255) {               // idle-warp poll thread: wait for chunk 0
        while (*(volatile int*)&g_chunk_done[0] < 32) __nanosleep(128);
    }
    __syncthreads();

    int pb = 0;
    for (int t = 0; t < T; ++t) {
        if (worker) {
            // L2-level load: produced by other SMs; also keeps 16MB stream out of L1.
            const float2* iinp = (const float2*)(g_Iin + ((size_t)t * Bdim + b) * Hdim + 2 * j);
            float2 iin;
            asm volatile("ld.global.cg.v2.f32 {%0,%1}, [%2];"
                         : "=f"(iin.x), "=f"(iin.y) : "l"(iinp));

            uint4 ma = *(uint4*)&masks[pb * 8];
            uint4 mb = *(uint4*)&masks[pb * 8 + 4];
            unsigned mw[8] = {ma.x, ma.y, ma.z, ma.w, mb.x, mb.y, mb.z, mb.w};

            // Sparse gather: word wp=2w+p covers presyn k = 64w + 2*bit + p.
            float r0 = 0.f, r1 = 0.f;
            const char* basej = (const char*)Wsh + (j << 3);
#pragma unroll
            for (int wp = 0; wp < 8; ++wp) {
                unsigned mm = mw[wp];
                if (wp >= 6) mm &= 0xFFFFu;          // k>=224 handled via regs
                const char* basew = basej + ((((wp >> 1) * 64) + (wp & 1)) << 10);
                while (mm) {
                    int bit = __ffs(mm) - 1;
                    mm &= mm - 1;
                    float2 wv = *(const float2*)(basew + (bit << 11));
                    r0 += wv.x; r1 += wv.y;
                }
            }
            // Register rows k in [224,256): word6 hi bits -> even rows, word7 -> odd.
            float rh0 = 0.f, rh1 = 0.f;
            unsigned he = mw[6] >> 16, ho = mw[7] >> 16;
#pragma unroll
            for (int bi = 0; bi < 16; ++bi) {
                if ((he >> bi) & 1u) { rh0 += wreg[2 * bi].x;     rh1 += wreg[2 * bi].y; }
                if ((ho >> bi) & 1u) { rh0 += wreg[2 * bi + 1].x; rh1 += wreg[2 * bi + 1].y; }
            }
            r0 += rh0; r1 += rh1;

            // LIF update (exact arithmetic forms validated in R1).
            float vd0 = v0r + 0.1f * ((0.0f - v0r) + c0);
            float vd1 = v1r + 0.1f * ((0.0f - v1r) + c1);
            float id0 = c0 - 0.2f * c0;
            float id1 = c1 - 0.2f * c1;
            zA = (vd0 - 1.0f) > 0.0f;
            zB = (vd1 - 1.0f) > 0.0f;
            v0r = zA ? 0.0f : vd0;
            v1r = zB ? 0.0f : vd1;
            c0 = (id0 + iin.x) + r0;
            c1 = (id1 + iin.y) + r1;

            unsigned nA = __ballot_sync(0xffffffffu, zA);
            unsigned nB = __ballot_sync(0xffffffffu, zB);
            if (lane == 0) {
                masks[(pb ^ 1) * 8 + 2 * warp]     = nA;
                masks[(pb ^ 1) * 8 + 2 * warp + 1] = nB;
            }
            float2 ov;
            ov.x = zA ? 1.0f : 0.0f;
            ov.y = zB ? 1.0f : 0.0f;
            *(float2*)(out + ((size_t)t * Bdim + b) * Hdim + 2 * j) = ov;
        } else if (tid == 255) {
            int tn = t + 1;                        // ensure next step's chunk is ready
            if (tn < T && (tn & 63) == 0) {
                while (*(volatile int*)&g_chunk_done[tn >> 6] < 32) __nanosleep(128);
            }
        }
        __syncthreads();                           // publish masks; gate data readiness
        pb ^= 1;
    }

    if (worker) {                                  // final state: [z][v][i] after spikes
        size_t base = (size_t)T * Bdim * Hdim;
        float2 zf; zf.x = zA ? 1.0f : 0.0f; zf.y = zB ? 1.0f : 0.0f;
        *(float2*)(out + base + b * Hdim + 2 * j)                   = zf;
        *(float2*)(out + base + Bdim * Hdim + b * Hdim + 2 * j)     = make_float2(v0r, v1r);
        *(float2*)(out + base + 2 * Bdim * Hdim + b * Hdim + 2 * j) = make_float2(c0, c1);
    }
}

extern "C" void kernel_launch(void* const* d_in, const int* in_sizes, int n_in,
                              void* d_out, int out_size)
{
    const float* x    = (const float*)d_in[0];   // (T,B,IN)
    const float* z0   = (const float*)d_in[1];   // (B,H)
    const float* v0   = (const float*)d_in[2];
    const float* i0   = (const float*)d_in[3];
    const float* Win  = (const float*)d_in[4];   // (H,IN)
    const float* Wrec = (const float*)d_in[5];   // (H,H)
    float* out = (float*)d_out;

    int T = in_sizes[0] / (Bdim * INdim);        // 2048

    int sms = 148;
    cudaDeviceGetAttribute(&sms, cudaDevAttrMultiProcessorCount, 0);

    cudaFuncSetAttribute(fused_kernel,
                         cudaFuncAttributeMaxDynamicSharedMemorySize, LOOP_SMEM);

    init_kernel<<<64, 256>>>(Wrec);
    fused_kernel<<<sms, 256, LOOP_SMEM>>>(x, z0, v0, i0, Win, out, T);

    (void)n_in; (void)out_size;
}

// round 4
// speedup vs baseline: 1.3388x; 1.3388x over previous
#include <cuda_runtime.h>

#define Bdim  32
#define Hdim  256
#define INdim 256
#define T_MAX 2048
#define KS    224                      // W_rec^T rows kept in shared memory
#define NLOOP 32                       // loop CTAs (one per batch)
#define LOOP_SMEM (KS * Hdim * 4 + 64) // 229440 <= 232448 (227KB cap)

__device__ float g_Iin[(size_t)T_MAX * Bdim * Hdim];  // input currents (t,b,h)
__device__ float g_WT[Hdim * Hdim];                    // WT[k][h] = Wrec[h][k]
__device__ int   g_chunk_done[64];                     // tiles finished per 64-step chunk

__global__ void init_kernel(const float* __restrict__ Wrec)
{
    int tid = blockIdx.x * blockDim.x + threadIdx.x;
    if (tid < 64) g_chunk_done[tid] = 0;
    for (int idx = tid; idx < Hdim * Hdim; idx += gridDim.x * blockDim.x) {
        int k = idx >> 8;
        int h = idx & 255;
        g_WT[idx] = Wrec[h * Hdim + k];
    }
}

// ---------------------------------------------------------------------------
// Fused persistent kernel. blockIdx < NLOOP: LIF recurrence (1 CTA / batch).
// blockIdx >= NLOOP: fp32 NT GEMM into g_Iin, t-major tiles, per-64-step
// chunk counters. 227KB smem forces 1 CTA/SM; grid == #SMs -> co-resident.
// ---------------------------------------------------------------------------
__global__ __launch_bounds__(256, 1) void fused_kernel(
    const float* __restrict__ x,   const float* __restrict__ z0,
    const float* __restrict__ v0,  const float* __restrict__ i0,
    const float* __restrict__ Win, float* __restrict__ out, int T)
{
    extern __shared__ float smem[];
    const int tid = threadIdx.x;

    if (blockIdx.x >= NLOOP) {
        // ================= GEMM producer =================
        float (*As)[132] = (float (*)[132])smem;
        float (*Bs)[132] = (float (*)[132])(smem + 32 * 132);
        const int g  = blockIdx.x - NLOOP;
        const int NG = gridDim.x - NLOOP;
        const int M  = T * Bdim;
        const int ntiles = (M / 128) * (Hdim / 128);
        const int tx = tid & 15;
        const int ty = tid >> 4;

        for (int tile = g; tile < ntiles; tile += NG) {
            const int m0 = (tile >> 1) * 128;
            const int n0 = (tile & 1) * 128;
            float acc[8][8];
#pragma unroll
            for (int r = 0; r < 8; ++r)
#pragma unroll
                for (int c = 0; c < 8; ++c) acc[r][c] = 0.0f;

            for (int k0 = 0; k0 < INdim; k0 += 32) {
#pragma unroll
                for (int i = 0; i < 4; ++i) {
                    int idx = tid + i * 256;
                    int row = idx >> 3;
                    int c4  = idx & 7;
                    float4 av = *(const float4*)(x + (size_t)(m0 + row) * INdim + k0 + c4 * 4);
                    As[c4 * 4 + 0][row] = av.x;
                    As[c4 * 4 + 1][row] = av.y;
                    As[c4 * 4 + 2][row] = av.z;
                    As[c4 * 4 + 3][row] = av.w;
                    float4 bv = *(const float4*)(Win + (size_t)(n0 + row) * INdim + k0 + c4 * 4);
                    Bs[c4 * 4 + 0][row] = bv.x;
                    Bs[c4 * 4 + 1][row] = bv.y;
                    Bs[c4 * 4 + 2][row] = bv.z;
                    Bs[c4 * 4 + 3][row] = bv.w;
                }
                __syncthreads();
#pragma unroll
                for (int k = 0; k < 32; ++k) {
                    float a[8], b[8];
#pragma unroll
                    for (int u = 0; u < 8; u += 4) {
                        float4 t4 = *(const float4*)&As[k][ty * 8 + u];
                        a[u] = t4.x; a[u + 1] = t4.y; a[u + 2] = t4.z; a[u + 3] = t4.w;
                        float4 s4 = *(const float4*)&Bs[k][tx * 8 + u];
                        b[u] = s4.x; b[u + 1] = s4.y; b[u + 2] = s4.z; b[u + 3] = s4.w;
                    }
#pragma unroll
                    for (int r = 0; r < 8; ++r)
#pragma unroll
                        for (int c = 0; c < 8; ++c)
                            acc[r][c] = fmaf(a[r], b[c], acc[r][c]);
                }
                __syncthreads();
            }
#pragma unroll
            for (int r = 0; r < 8; ++r)
#pragma unroll
                for (int c = 0; c < 8; c += 4) {
                    float4 o = make_float4(acc[r][c], acc[r][c + 1], acc[r][c + 2], acc[r][c + 3]);
                    *(float4*)(g_Iin + (size_t)(m0 + ty * 8 + r) * Hdim + n0 + tx * 8 + c) = o;
                }
            __threadfence();
            __syncthreads();
            if (tid == 0) atomicAdd(&g_chunk_done[m0 >> 11], 1);  // chunk = t/64
        }
        return;
    }

    // ================= LIF recurrence consumer =================
    const int b = blockIdx.x;
    float*    Wsh   = smem;                              // [KS][Hdim]
    unsigned* masks = (unsigned*)(smem + KS * Hdim);     // [2][8] spike bitmasks

    for (int idx = tid; idx < KS * Hdim / 4; idx += 256)
        ((float4*)Wsh)[idx] = ((const float4*)g_WT)[idx];

    const bool worker = tid < 128;
    const int  j    = tid;          // worker's pair index: neurons 2j, 2j+1
    const int  warp = tid >> 5;
    const int  lane = tid & 31;

    float v0r = 0.f, v1r = 0.f, c0 = 0.f, c1 = 0.f;
    float2 wreg[32];                // rows [KS,256) for cols 2j,2j+1
    bool zA = false, zB = false;

    if (worker) {
        float2 zz = *(const float2*)(z0 + b * Hdim + 2 * j);
        float2 vv = *(const float2*)(v0 + b * Hdim + 2 * j);
        float2 ii = *(const float2*)(i0 + b * Hdim + 2 * j);
        v0r = vv.x; v1r = vv.y; c0 = ii.x; c1 = ii.y;
        unsigned mA = __ballot_sync(0xffffffffu, zz.x != 0.0f);
        unsigned mB = __ballot_sync(0xffffffffu, zz.y != 0.0f);
        if (lane == 0) { masks[2 * warp] = mA; masks[2 * warp + 1] = mB; }
#pragma unroll
        for (int r = 0; r < 32; ++r)
            wreg[r] = *(const float2*)(g_WT + (size_t)(KS + r) * Hdim + 2 * j);
    }
    if (tid == 255) {               // poll: chunk 0 must exist before prefetches
        while (*(volatile int*)&g_chunk_done[0] < 32) __nanosleep(128);
    }
    __syncthreads();

    // 2-deep input-current prefetch pipeline (L2-level loads).
    float2 f0 = make_float2(0.f, 0.f), f1 = make_float2(0.f, 0.f);
    if (worker) {
        const float* p0 = g_Iin + ((size_t)0 * Bdim + b) * Hdim + 2 * j;
        asm volatile("ld.global.cg.v2.f32 {%0,%1}, [%2];" : "=f"(f0.x), "=f"(f0.y) : "l"(p0));
        if (T > 1) {
            const float* p1 = g_Iin + ((size_t)1 * Bdim + b) * Hdim + 2 * j;
            asm volatile("ld.global.cg.v2.f32 {%0,%1}, [%2];" : "=f"(f1.x), "=f"(f1.y) : "l"(p1));
        }
    }

    int pb = 0;
    for (int t = 0; t < T; ++t) {
        if (worker) {
            // Prefetch step t+2 (consumed two barriers later; hides L2/DRAM).
            float2 f2 = make_float2(0.f, 0.f);
            if (t + 2 < T) {
                const float* p2 = g_Iin + ((size_t)(t + 2) * Bdim + b) * Hdim + 2 * j;
                asm volatile("ld.global.cg.v2.f32 {%0,%1}, [%2];"
                             : "=f"(f2.x), "=f"(f2.y) : "l"(p2));
            }

            uint4 ma = *(uint4*)&masks[pb * 8];
            uint4 mb = *(uint4*)&masks[pb * 8 + 4];
            unsigned mw[8] = {ma.x, ma.y, ma.z, ma.w, mb.x, mb.y, mb.z, mb.w};

            // Sparse gather: word wp covers presyn k = 64*(wp>>1) + 2*bit + (wp&1).
            // Unrolled 2 spikes/iter, 4 accumulators (halve branches, break chains).
            float a0 = 0.f, a1 = 0.f, a2 = 0.f, a3 = 0.f;
            const char* basej = (const char*)Wsh + (j << 3);
#pragma unroll
            for (int wp = 0; wp < 8; ++wp) {
                unsigned mm = mw[wp];
                if (wp >= 6) mm &= 0xFFFFu;          // k>=224 handled via regs
                const char* basew = basej + ((((wp >> 1) * 64) + (wp & 1)) << 10);
                while (mm) {
                    int b0 = __ffs(mm) - 1;
                    mm &= mm - 1;
                    float2 w0 = *(const float2*)(basew + (b0 << 11));
                    a0 += w0.x; a1 += w0.y;
                    if (mm) {
                        int b1 = __ffs(mm) - 1;
                        mm &= mm - 1;
                        float2 w1 = *(const float2*)(basew + (b1 << 11));
                        a2 += w1.x; a3 += w1.y;
                    }
                }
            }
            // Register rows k in [224,256): word6 hi bits -> even, word7 -> odd.
            unsigned he = mw[6] >> 16, ho = mw[7] >> 16;
#pragma unroll
            for (int bi = 0; bi < 16; ++bi) {
                if ((he >> bi) & 1u) { a0 += wreg[2 * bi].x;     a1 += wreg[2 * bi].y; }
                if ((ho >> bi) & 1u) { a2 += wreg[2 * bi + 1].x; a3 += wreg[2 * bi + 1].y; }
            }
            float r0 = a0 + a2, r1 = a1 + a3;

            // LIF update (exact arithmetic forms validated in R1/R3).
            float vd0 = v0r + 0.1f * ((0.0f - v0r) + c0);
            float vd1 = v1r + 0.1f * ((0.0f - v1r) + c1);
            float id0 = c0 - 0.2f * c0;
            float id1 = c1 - 0.2f * c1;
            zA = (vd0 - 1.0f) > 0.0f;
            zB = (vd1 - 1.0f) > 0.0f;
            v0r = zA ? 0.0f : vd0;
            v1r = zB ? 0.0f : vd1;
            c0 = (id0 + f0.x) + r0;
            c1 = (id1 + f0.y) + r1;

            unsigned nA = __ballot_sync(0xffffffffu, zA);
            unsigned nB = __ballot_sync(0xffffffffu, zB);
            if (lane == 0) {
                masks[(pb ^ 1) * 8 + 2 * warp]     = nA;
                masks[(pb ^ 1) * 8 + 2 * warp + 1] = nB;
            }
            float2 ov;
            ov.x = zA ? 1.0f : 0.0f;
            ov.y = zB ? 1.0f : 0.0f;
            *(float2*)(out + ((size_t)t * Bdim + b) * Hdim + 2 * j) = ov;

            f0 = f1;
            f1 = f2;
        } else if (tid == 255) {
            // Ensure chunk (t>>6)+1 done before any worker loads into it
            // (loads for t'+2 first touch chunk c+1 at t' = 64c+62 > 64c+60).
            if ((t & 63) == 60) {
                int nc = (t >> 6) + 1;
                if (nc < (T >> 6)) {
                    while (*(volatile int*)&g_chunk_done[nc] < 32) __nanosleep(128);
                }
            }
        }
        __syncthreads();                           // publish masks; gate readiness
        pb ^= 1;
    }

    if (worker) {                                  // final state: [z][v][i] after spikes
        size_t base = (size_t)T * Bdim * Hdim;
        float2 zf; zf.x = zA ? 1.0f : 0.0f; zf.y = zB ? 1.0f : 0.0f;
        *(float2*)(out + base + b * Hdim + 2 * j)                   = zf;
        *(float2*)(out + base + Bdim * Hdim + b * Hdim + 2 * j)     = make_float2(v0r, v1r);
        *(float2*)(out + base + 2 * Bdim * Hdim + b * Hdim + 2 * j) = make_float2(c0, c1);
    }
}

extern "C" void kernel_launch(void* const* d_in, const int* in_sizes, int n_in,
                              void* d_out, int out_size)
{
    const float* x    = (const float*)d_in[0];   // (T,B,IN)
    const float* z0   = (const float*)d_in[1];   // (B,H)
    const float* v0   = (const float*)d_in[2];
    const float* i0   = (const float*)d_in[3];
    const float* Win  = (const float*)d_in[4];   // (H,IN)
    const float* Wrec = (const float*)d_in[5];   // (H,H)
    float* out = (float*)d_out;

    int T = in_sizes[0] / (Bdim * INdim);        // 2048

    int sms = 148;
    cudaDeviceGetAttribute(&sms, cudaDevAttrMultiProcessorCount, 0);

    cudaFuncSetAttribute(fused_kernel,
                         cudaFuncAttributeMaxDynamicSharedMemorySize, LOOP_SMEM);

    init_kernel<<<64, 256>>>(Wrec);
    fused_kernel<<<sms, 256, LOOP_SMEM>>>(x, z0, v0, i0, Win, out, T);

    (void)n_in; (void)out_size;
}